// round 12
// baseline (speedup 1.0000x reference)
#include <cuda_runtime.h>

// ADI diffusion, Neumann-series tridiagonal solves.
// B=16, C=8, S=128. 10 steps of [mix, x-half, y-full, x-half].
//
// Numerics: the reference's (denom+EPS) Thomas == Thomas on the system with
// diagonal b+1e-6. Off-diag/diag ratio ~1e-3, so the truncated series
// x = (I + N + N^2 + N^3) B^-1 d (N = -B^-1 A_off) is exact to ~1e-11/sweep.
//
// x sweeps: warp-per-row, lane owns 4 contiguous w, neighbor exchange by shfl,
//           trailing-x + channel-mix + leading-x fused per step (row-local).
// y sweep:  the SAME series expanded in closed form as a one-shot 7-tap
//           stencil along h. One sync, no iteration, no transpose.
//           NOTE: no min-blocks launch bound — forcing 32 regs spilled to
//           local memory (R11: L2% 2.4x, issue 25%). Let ptxas use ~44 regs.

#define S_DIM 128
#define C_DIM 8
#define B_DIM 16
#define EPSF 1e-6f
#define FULLMASK 0xffffffffu

// ---------------- float4 helpers ----------------
__device__ __forceinline__ float4 f4add(float4 a, float4 b) {
    return make_float4(a.x + b.x, a.y + b.y, a.z + b.z, a.w + b.w);
}
__device__ __forceinline__ float4 f4mul(float4 a, float4 b) {
    return make_float4(a.x * b.x, a.y * b.y, a.z * b.z, a.w * b.w);
}
__device__ __forceinline__ float4 f4fma(float4 a, float4 b, float4 c) {
    return make_float4(fmaf(a.x, b.x, c.x), fmaf(a.y, b.y, c.y),
                       fmaf(a.z, b.z, c.z), fmaf(a.w, b.w, c.w));
}
__device__ __forceinline__ float4 f4fmas(float s, float4 b, float4 c) {
    return make_float4(fmaf(s, b.x, c.x), fmaf(s, b.y, c.y),
                       fmaf(s, b.z, c.z), fmaf(s, b.w, c.w));
}
__device__ __forceinline__ float4 f4adds(float4 a, float s) {
    return make_float4(a.x + s, a.y + s, a.z + s, a.w + s);
}
__device__ __forceinline__ float4 f4coeff(float4 b4, float4 t4, float t,
                                          float scale) {
    float4 r;
    r.x = fminf(fmaxf(fmaf(t4.x, t, b4.x), EPSF), 10.0f) * scale;
    r.y = fminf(fmaxf(fmaf(t4.y, t, b4.y), EPSF), 10.0f) * scale;
    r.z = fminf(fmaxf(fmaf(t4.z, t, b4.z), EPSF), 10.0f) * scale;
    r.w = fminf(fmaxf(fmaf(t4.w, t, b4.w), EPSF), 10.0f) * scale;
    return r;
}

// ---------------- warp Neumann solve (x direction) ----------------
__device__ __forceinline__ void neumann_line(const float co[4], float d[4],
                                             int lane) {
    float w[4], y[4], acc[4];
#pragma unroll
    for (int r = 0; r < 4; r++) {
        int i = lane * 4 + r;
        float cr = co[r];
        float b = (i == 0 || i == S_DIM - 1) ? (1.0f + cr) : (1.0f + 2.0f * cr);
        b += EPSF;
        float g = __fdividef(1.0f, b);
        w[r] = cr * g;
        y[r] = d[r] * g;
        acc[r] = y[r];
    }
#pragma unroll
    for (int k = 0; k < 3; k++) {
        float up = __shfl_up_sync(FULLMASK, y[3], 1);
        float dn = __shfl_down_sync(FULLMASK, y[0], 1);
        if (lane == 0) up = 0.0f;
        if (lane == 31) dn = 0.0f;
        float n0 = w[0] * (up + y[1]);
        float n1 = w[1] * (y[0] + y[2]);
        float n2 = w[2] * (y[1] + y[3]);
        float n3 = w[3] * (y[2] + dn);
        y[0] = n0; y[1] = n1; y[2] = n2; y[3] = n3;
        acc[0] += n0; acc[1] += n1; acc[2] += n2; acc[3] += n3;
    }
#pragma unroll
    for (int r = 0; r < 4; r++) d[r] = acc[r];
}

__device__ __forceinline__ void solve_x4(float4 co4, float4& dd, int lane) {
    float co[4] = {co4.x, co4.y, co4.z, co4.w};
    float d[4] = {dd.x, dd.y, dd.z, dd.w};
    neumann_line(co, d, lane);
    dd = make_float4(d[0], d[1], d[2], d[3]);
}

// ---------------- x-direction kernels ----------------
#define XPITCH 132

__global__ void __launch_bounds__(512) k_mix_x(
    const float* __restrict__ u_in, const float* __restrict__ M,
    const float* __restrict__ ab, const float* __restrict__ atc,
    float* __restrict__ u_out, float t) {
    __shared__ __align__(16) float sx[16 * XPITCH];
    __shared__ float sM[64];
    int tid = threadIdx.x, lane = tid & 31, w = tid >> 5;
    int b = blockIdx.x, h0 = blockIdx.y * 2;
    int c = w >> 1, hh = w & 1, h = h0 + hh;
    if (tid < 64) sM[tid] = M[tid];
    int rowbase = (((b * C_DIM + c) * S_DIM) + h) * S_DIM;
    int crowbase = ((c * S_DIM) + h) * S_DIM;
    float4 u4 = *reinterpret_cast<const float4*>(u_in + rowbase + 4 * lane);
    *reinterpret_cast<float4*>(&sx[w * XPITCH + 4 * lane]) = u4;
    float4 co = f4coeff(
        *reinterpret_cast<const float4*>(ab + crowbase + 4 * lane),
        *reinterpret_cast<const float4*>(atc + crowbase + 4 * lane), t,
        0.0005f);
    __syncthreads();
    float4 d = make_float4(0.f, 0.f, 0.f, 0.f);
#pragma unroll
    for (int cc = 0; cc < 8; cc++) {
        float m = sM[c * 8 + cc];
        float4 s4 = *reinterpret_cast<const float4*>(
            &sx[(cc * 2 + hh) * XPITCH + 4 * lane]);
        d = f4fmas(m, s4, d);
    }
    solve_x4(co, d, lane);
    *reinterpret_cast<float4*>(u_out + rowbase + 4 * lane) = d;
}

__global__ void __launch_bounds__(512) k_x_mix_x(
    float* __restrict__ u, const float* __restrict__ M,
    const float* __restrict__ ab, const float* __restrict__ atc, float t) {
    __shared__ __align__(16) float sx[16 * XPITCH];
    __shared__ float sM[64];
    int tid = threadIdx.x, lane = tid & 31, w = tid >> 5;
    int b = blockIdx.x, h0 = blockIdx.y * 2;
    int c = w >> 1, hh = w & 1, h = h0 + hh;
    if (tid < 64) sM[tid] = M[tid];
    int rowbase = (((b * C_DIM + c) * S_DIM) + h) * S_DIM;
    int crowbase = ((c * S_DIM) + h) * S_DIM;
    float4 d = *reinterpret_cast<const float4*>(u + rowbase + 4 * lane);
    float4 co = f4coeff(
        *reinterpret_cast<const float4*>(ab + crowbase + 4 * lane),
        *reinterpret_cast<const float4*>(atc + crowbase + 4 * lane), t,
        0.0005f);
    solve_x4(co, d, lane);  // trailing x of step k
    *reinterpret_cast<float4*>(&sx[w * XPITCH + 4 * lane]) = d;
    __syncthreads();
    float4 d2 = make_float4(0.f, 0.f, 0.f, 0.f);
#pragma unroll
    for (int cc = 0; cc < 8; cc++) {
        float m = sM[c * 8 + cc];
        float4 s4 = *reinterpret_cast<const float4*>(
            &sx[(cc * 2 + hh) * XPITCH + 4 * lane]);
        d2 = f4fmas(m, s4, d2);
    }
    solve_x4(co, d2, lane);  // leading x of step k+1 (same alpha t)
    *reinterpret_cast<float4*>(u + rowbase + 4 * lane) = d2;
}

__global__ void __launch_bounds__(512) k_x(
    float* __restrict__ u, const float* __restrict__ ab,
    const float* __restrict__ atc, float t) {
    int tid = threadIdx.x, lane = tid & 31, w = tid >> 5;
    int b = blockIdx.x, h0 = blockIdx.y * 2;
    int c = w >> 1, hh = w & 1, h = h0 + hh;
    int rowbase = (((b * C_DIM + c) * S_DIM) + h) * S_DIM;
    int crowbase = ((c * S_DIM) + h) * S_DIM;
    float4 d = *reinterpret_cast<const float4*>(u + rowbase + 4 * lane);
    float4 co = f4coeff(
        *reinterpret_cast<const float4*>(ab + crowbase + 4 * lane),
        *reinterpret_cast<const float4*>(atc + crowbase + 4 * lane), t,
        0.0005f);
    solve_x4(co, d, lane);
    *reinterpret_cast<float4*>(u + rowbase + 4 * lane) = d;
}

// ---------------- y-direction kernel: one-shot 7-tap ----------------
// Block = (b, c, 32-col slab), 512 threads, 2 float4 per thread.
// Stage y0 = u/b and w = co/b into padded smem (zero borders), then
// out[h] = (1+g)*y0[h] + W1m*y0[h-1] + W1p*y0[h+1] + W2m*y0[h-2]
//        + W2p*y0[h+2] + W3m*y0[h-3] + W3p*y0[h+3],
// g = p0(pm1+pp1); W1± = p0(1+g+p±1 p±2); W2± = p0 p±1; W3± = p0 p±1 p±2.
// Padded rows make all tap loads unconditional. One __syncthreads().

#define Y0_ROWS (S_DIM + 6)   // h+3 offset
#define W_ROWS (S_DIM + 4)    // h+2 offset

__global__ void __launch_bounds__(512) k_y(
    float* __restrict__ u, const float* __restrict__ bb,
    const float* __restrict__ btc, float t) {
    __shared__ __align__(16) float4 sy0[Y0_ROWS * 8];
    __shared__ __align__(16) float4 sw[W_ROWS * 8];
    int tid = threadIdx.x;
    int b = blockIdx.x, c = blockIdx.y, w0 = blockIdx.z * 32;
    const float4* __restrict__ uP = reinterpret_cast<const float4*>(
        u + (b * C_DIM + c) * S_DIM * S_DIM + w0);
    const float4* __restrict__ bbP = reinterpret_cast<const float4*>(
        bb + c * S_DIM * S_DIM + w0);
    const float4* __restrict__ btP = reinterpret_cast<const float4*>(
        btc + c * S_DIM * S_DIM + w0);

    // zero borders: sy0 rows 0..2 & 131..133 (48 f4), sw rows 0..1 & 130..131
    if (tid < 48) {
        int i = (tid < 24) ? tid : (131 * 8 + tid - 24);
        sy0[i] = make_float4(0.f, 0.f, 0.f, 0.f);
    } else if (tid < 80) {
        int j = tid - 48;
        int i = (j < 16) ? j : (130 * 8 + j - 16);
        sw[i] = make_float4(0.f, 0.f, 0.f, 0.f);
    }
#pragma unroll
    for (int k = 0; k < 2; k++) {
        int e = tid + k * 512;
        int h = e >> 3, g = e & 7;
        int gidx = h * 32 + g;
        float4 u4 = uP[gidx];
        float4 co = f4coeff(bbP[gidx], btP[gidx], t, 0.001f);  // DT/DY^2
        float edgef = (h == 0 || h == S_DIM - 1) ? 1.0f : 2.0f;
        float4 y0, wv;
        float bd, inv;
        bd = fmaf(edgef, co.x, 1.0f) + EPSF; inv = __fdividef(1.0f, bd);
        y0.x = u4.x * inv; wv.x = co.x * inv;
        bd = fmaf(edgef, co.y, 1.0f) + EPSF; inv = __fdividef(1.0f, bd);
        y0.y = u4.y * inv; wv.y = co.y * inv;
        bd = fmaf(edgef, co.z, 1.0f) + EPSF; inv = __fdividef(1.0f, bd);
        y0.z = u4.z * inv; wv.z = co.z * inv;
        bd = fmaf(edgef, co.w, 1.0f) + EPSF; inv = __fdividef(1.0f, bd);
        y0.w = u4.w * inv; wv.w = co.w * inv;
        sy0[(h + 3) * 8 + g] = y0;
        sw[(h + 2) * 8 + g] = wv;
    }
    __syncthreads();

    float4* __restrict__ uOut = reinterpret_cast<float4*>(
        u + (b * C_DIM + c) * S_DIM * S_DIM + w0);
#pragma unroll
    for (int k = 0; k < 2; k++) {
        int e = tid + k * 512;
        int h = e >> 3, g = e & 7;
        int by = (h + 3) * 8 + g;
        int bw = (h + 2) * 8 + g;
        // accumulate taps in pairs so weight temporaries die immediately
        float4 P1 = sw[bw - 8], P2 = sw[bw], P3 = sw[bw + 8];
        float4 gg = f4mul(P2, f4add(P1, P3));
        float4 one_g = f4adds(gg, 1.0f);
        float4 acc = f4mul(one_g, sy0[by]);
        {
            float4 P0 = sw[bw - 16];
            float4 Wm2 = f4mul(P2, P1);
            acc = f4fma(f4mul(P2, f4fma(P1, P0, one_g)), sy0[by - 8], acc);
            acc = f4fma(Wm2, sy0[by - 16], acc);
            acc = f4fma(f4mul(Wm2, P0), sy0[by - 24], acc);
        }
        {
            float4 P4 = sw[bw + 16];
            float4 Wp2 = f4mul(P2, P3);
            acc = f4fma(f4mul(P2, f4fma(P3, P4, one_g)), sy0[by + 8], acc);
            acc = f4fma(Wp2, sy0[by + 16], acc);
            acc = f4fma(f4mul(Wp2, P4), sy0[by + 24], acc);
        }
        uOut[h * 32 + g] = acc;
    }
}

// ---------------- Launch ----------------

extern "C" void kernel_launch(void* const* d_in, const int* in_sizes, int n_in,
                              void* d_out, int out_size) {
    const float* u = (const float*)d_in[0];
    const float* ab = (const float*)d_in[1];
    const float* bb = (const float*)d_in[2];
    const float* atc = (const float*)d_in[3];
    const float* btc = (const float*)d_in[4];
    const float* M = (const float*)d_in[5];
    float* out = (float*)d_out;

    dim3 gx(B_DIM, S_DIM / 2);   // 1024 blocks
    dim3 gy(B_DIM, C_DIM, 4);    // 512 blocks (32-col slabs)

    const double DTd = 0.001, halfd = 0.0005;

    k_mix_x<<<gx, 512>>>(u, M, ab, atc, out, 0.0f);
    for (int k = 0; k < 10; k++) {
        k_y<<<gy, 512>>>(out, bb, btc, (float)(k * DTd + halfd));
        if (k < 9)
            k_x_mix_x<<<gx, 512>>>(out, M, ab, atc, (float)((k + 1) * DTd));
    }
    k_x<<<gx, 512>>>(out, ab, atc, (float)(10 * DTd));
}

// round 16
// speedup vs baseline: 1.6332x; 1.6332x over previous
#include <cuda_runtime.h>

// ADI diffusion, Neumann-series tridiagonal solves.
// B=16, C=8, S=128. 10 steps of [mix, x-half, y-full, x-half].
//
// Numerics: the reference's (denom+EPS) Thomas == Thomas on the system with
// diagonal b+1e-6. Off-diag/diag ratio ~1e-3, so the truncated series
// x = (I + N + N^2 + N^3) B^-1 d (N = -B^-1 A_off) is exact to ~1e-11/sweep.
//
// x sweeps: warp-per-row, lane owns 4 contiguous w, neighbor exchange by shfl,
//           trailing-x + channel-mix + leading-x fused per step (row-local).
// y sweep:  3 Jacobi-style stencil sweeps along h in smem ping-pong buffers.
//           512 threads, ONE float4 per thread (16-col slab, 128 rows x 4 f4).
//           R14 bug: same indexing launched with 256 threads -> half the tile
//           unprocessed. Fixed: block size must equal 128*4 = 512.

#define S_DIM 128
#define C_DIM 8
#define B_DIM 16
#define EPSF 1e-6f
#define FULLMASK 0xffffffffu

// ---------------- float4 helpers ----------------
__device__ __forceinline__ float4 f4fmas(float s, float4 b, float4 c) {
    return make_float4(fmaf(s, b.x, c.x), fmaf(s, b.y, c.y),
                       fmaf(s, b.z, c.z), fmaf(s, b.w, c.w));
}
__device__ __forceinline__ float4 f4coeff(float4 b4, float4 t4, float t,
                                          float scale) {
    float4 r;
    r.x = fminf(fmaxf(fmaf(t4.x, t, b4.x), EPSF), 10.0f) * scale;
    r.y = fminf(fmaxf(fmaf(t4.y, t, b4.y), EPSF), 10.0f) * scale;
    r.z = fminf(fmaxf(fmaf(t4.z, t, b4.z), EPSF), 10.0f) * scale;
    r.w = fminf(fmaxf(fmaf(t4.w, t, b4.w), EPSF), 10.0f) * scale;
    return r;
}

// ---------------- warp Neumann solve (x direction) ----------------
__device__ __forceinline__ void neumann_line(const float co[4], float d[4],
                                             int lane) {
    float w[4], y[4], acc[4];
#pragma unroll
    for (int r = 0; r < 4; r++) {
        int i = lane * 4 + r;
        float cr = co[r];
        float b = (i == 0 || i == S_DIM - 1) ? (1.0f + cr) : (1.0f + 2.0f * cr);
        b += EPSF;
        float g = __fdividef(1.0f, b);
        w[r] = cr * g;
        y[r] = d[r] * g;
        acc[r] = y[r];
    }
#pragma unroll
    for (int k = 0; k < 3; k++) {
        float up = __shfl_up_sync(FULLMASK, y[3], 1);
        float dn = __shfl_down_sync(FULLMASK, y[0], 1);
        if (lane == 0) up = 0.0f;
        if (lane == 31) dn = 0.0f;
        float n0 = w[0] * (up + y[1]);
        float n1 = w[1] * (y[0] + y[2]);
        float n2 = w[2] * (y[1] + y[3]);
        float n3 = w[3] * (y[2] + dn);
        y[0] = n0; y[1] = n1; y[2] = n2; y[3] = n3;
        acc[0] += n0; acc[1] += n1; acc[2] += n2; acc[3] += n3;
    }
#pragma unroll
    for (int r = 0; r < 4; r++) d[r] = acc[r];
}

__device__ __forceinline__ void solve_x4(float4 co4, float4& dd, int lane) {
    float co[4] = {co4.x, co4.y, co4.z, co4.w};
    float d[4] = {dd.x, dd.y, dd.z, dd.w};
    neumann_line(co, d, lane);
    dd = make_float4(d[0], d[1], d[2], d[3]);
}

// ---------------- x-direction kernels ----------------
#define XPITCH 132

__global__ void __launch_bounds__(512) k_mix_x(
    const float* __restrict__ u_in, const float* __restrict__ M,
    const float* __restrict__ ab, const float* __restrict__ atc,
    float* __restrict__ u_out, float t) {
    __shared__ __align__(16) float sx[16 * XPITCH];
    __shared__ float sM[64];
    int tid = threadIdx.x, lane = tid & 31, w = tid >> 5;
    int b = blockIdx.x, h0 = blockIdx.y * 2;
    int c = w >> 1, hh = w & 1, h = h0 + hh;
    if (tid < 64) sM[tid] = M[tid];
    int rowbase = (((b * C_DIM + c) * S_DIM) + h) * S_DIM;
    int crowbase = ((c * S_DIM) + h) * S_DIM;
    float4 u4 = *reinterpret_cast<const float4*>(u_in + rowbase + 4 * lane);
    *reinterpret_cast<float4*>(&sx[w * XPITCH + 4 * lane]) = u4;
    float4 co = f4coeff(
        *reinterpret_cast<const float4*>(ab + crowbase + 4 * lane),
        *reinterpret_cast<const float4*>(atc + crowbase + 4 * lane), t,
        0.0005f);
    __syncthreads();
    float4 d = make_float4(0.f, 0.f, 0.f, 0.f);
#pragma unroll
    for (int cc = 0; cc < 8; cc++) {
        float m = sM[c * 8 + cc];
        float4 s4 = *reinterpret_cast<const float4*>(
            &sx[(cc * 2 + hh) * XPITCH + 4 * lane]);
        d = f4fmas(m, s4, d);
    }
    solve_x4(co, d, lane);
    *reinterpret_cast<float4*>(u_out + rowbase + 4 * lane) = d;
}

__global__ void __launch_bounds__(512) k_x_mix_x(
    float* __restrict__ u, const float* __restrict__ M,
    const float* __restrict__ ab, const float* __restrict__ atc, float t) {
    __shared__ __align__(16) float sx[16 * XPITCH];
    __shared__ float sM[64];
    int tid = threadIdx.x, lane = tid & 31, w = tid >> 5;
    int b = blockIdx.x, h0 = blockIdx.y * 2;
    int c = w >> 1, hh = w & 1, h = h0 + hh;
    if (tid < 64) sM[tid] = M[tid];
    int rowbase = (((b * C_DIM + c) * S_DIM) + h) * S_DIM;
    int crowbase = ((c * S_DIM) + h) * S_DIM;
    float4 d = *reinterpret_cast<const float4*>(u + rowbase + 4 * lane);
    float4 co = f4coeff(
        *reinterpret_cast<const float4*>(ab + crowbase + 4 * lane),
        *reinterpret_cast<const float4*>(atc + crowbase + 4 * lane), t,
        0.0005f);
    solve_x4(co, d, lane);  // trailing x of step k
    *reinterpret_cast<float4*>(&sx[w * XPITCH + 4 * lane]) = d;
    __syncthreads();
    float4 d2 = make_float4(0.f, 0.f, 0.f, 0.f);
#pragma unroll
    for (int cc = 0; cc < 8; cc++) {
        float m = sM[c * 8 + cc];
        float4 s4 = *reinterpret_cast<const float4*>(
            &sx[(cc * 2 + hh) * XPITCH + 4 * lane]);
        d2 = f4fmas(m, s4, d2);
    }
    solve_x4(co, d2, lane);  // leading x of step k+1 (same alpha t)
    *reinterpret_cast<float4*>(u + rowbase + 4 * lane) = d2;
}

__global__ void __launch_bounds__(512) k_x(
    float* __restrict__ u, const float* __restrict__ ab,
    const float* __restrict__ atc, float t) {
    int tid = threadIdx.x, lane = tid & 31, w = tid >> 5;
    int b = blockIdx.x, h0 = blockIdx.y * 2;
    int c = w >> 1, hh = w & 1, h = h0 + hh;
    int rowbase = (((b * C_DIM + c) * S_DIM) + h) * S_DIM;
    int crowbase = ((c * S_DIM) + h) * S_DIM;
    float4 d = *reinterpret_cast<const float4*>(u + rowbase + 4 * lane);
    float4 co = f4coeff(
        *reinterpret_cast<const float4*>(ab + crowbase + 4 * lane),
        *reinterpret_cast<const float4*>(atc + crowbase + 4 * lane), t,
        0.0005f);
    solve_x4(co, d, lane);
    *reinterpret_cast<float4*>(u + rowbase + 4 * lane) = d;
}

// ---------------- y-direction kernel (stencil, thin per-thread state) ------
// Block = (b, c, 16-col slab). 512 threads, ONE float4 per thread:
// h = tid>>2 in 0..127, g = tid&3. Weights/accumulator in registers; y
// ping-pongs between two 8KB smem buffers; taps at +-4 f4, 3 sweeps.

__global__ void __launch_bounds__(512) k_y(
    float* __restrict__ u, const float* __restrict__ bb,
    const float* __restrict__ btc, float t) {
    __shared__ __align__(16) float4 sA[512];
    __shared__ __align__(16) float4 sB[512];
    int tid = threadIdx.x;
    int h = tid >> 2, g = tid & 3;
    int b = blockIdx.x, c = blockIdx.y;
    int f4base = blockIdx.z * 4;  // 16-col slab -> 4 float4 per row
    int gidx = h * 32 + f4base + g;
    const float4* __restrict__ uP = reinterpret_cast<const float4*>(
        u + (b * C_DIM + c) * S_DIM * S_DIM);
    const float4* __restrict__ bbP = reinterpret_cast<const float4*>(
        bb + c * S_DIM * S_DIM);
    const float4* __restrict__ btP = reinterpret_cast<const float4*>(
        btc + c * S_DIM * S_DIM);

    float4 u4 = uP[gidx];
    float4 co = f4coeff(bbP[gidx], btP[gidx], t, 0.001f);  // DT/DY^2
    float edgef = (h == 0 || h == S_DIM - 1) ? 1.0f : 2.0f;
    float4 wgt, acc;
    {
        float bd, inv;
        bd = fmaf(edgef, co.x, 1.0f) + EPSF; inv = __fdividef(1.0f, bd);
        wgt.x = co.x * inv; acc.x = u4.x * inv;
        bd = fmaf(edgef, co.y, 1.0f) + EPSF; inv = __fdividef(1.0f, bd);
        wgt.y = co.y * inv; acc.y = u4.y * inv;
        bd = fmaf(edgef, co.z, 1.0f) + EPSF; inv = __fdividef(1.0f, bd);
        wgt.z = co.z * inv; acc.z = u4.z * inv;
        bd = fmaf(edgef, co.w, 1.0f) + EPSF; inv = __fdividef(1.0f, bd);
        wgt.w = co.w * inv; acc.w = u4.w * inv;
    }
    sA[tid] = acc;  // y0
    float4* cur = sA;
    float4* nxt = sB;
#pragma unroll
    for (int it = 0; it < 3; it++) {
        __syncthreads();
        float4 ym = (h > 0) ? cur[tid - 4] : make_float4(0.f, 0.f, 0.f, 0.f);
        float4 yp = (h < S_DIM - 1) ? cur[tid + 4]
                                    : make_float4(0.f, 0.f, 0.f, 0.f);
        float4 yn;
        yn.x = wgt.x * (ym.x + yp.x);
        yn.y = wgt.y * (ym.y + yp.y);
        yn.z = wgt.z * (ym.z + yp.z);
        yn.w = wgt.w * (ym.w + yp.w);
        acc.x += yn.x; acc.y += yn.y; acc.z += yn.z; acc.w += yn.w;
        if (it < 2) {
            nxt[tid] = yn;
            float4* tmp = cur; cur = nxt; nxt = tmp;
        }
    }
    float4* __restrict__ uOut = reinterpret_cast<float4*>(
        u + (b * C_DIM + c) * S_DIM * S_DIM);
    uOut[gidx] = acc;
}

// ---------------- Launch ----------------

extern "C" void kernel_launch(void* const* d_in, const int* in_sizes, int n_in,
                              void* d_out, int out_size) {
    const float* u = (const float*)d_in[0];
    const float* ab = (const float*)d_in[1];
    const float* bb = (const float*)d_in[2];
    const float* atc = (const float*)d_in[3];
    const float* btc = (const float*)d_in[4];
    const float* M = (const float*)d_in[5];
    float* out = (float*)d_out;

    dim3 gx(B_DIM, S_DIM / 2);       // 1024 blocks
    dim3 gy(B_DIM, C_DIM, 8);        // 1024 blocks (16-col slabs)

    const double DTd = 0.001, halfd = 0.0005;

    k_mix_x<<<gx, 512>>>(u, M, ab, atc, out, 0.0f);
    for (int k = 0; k < 10; k++) {
        k_y<<<gy, 512>>>(out, bb, btc, (float)(k * DTd + halfd));
        if (k < 9)
            k_x_mix_x<<<gx, 512>>>(out, M, ab, atc, (float)((k + 1) * DTd));
    }
    k_x<<<gx, 512>>>(out, ab, atc, (float)(10 * DTd));
}